// round 1
// baseline (speedup 1.0000x reference)
#include <cuda_runtime.h>
#include <cuda_bf16.h>
#include <math.h>

#define N_NODES 131072
#define N_EDGES 2097152
#define N_GRAPHS 2048
#define IN_CH 12
#define HID 64
#define OUT_CH 4

// Scratch (device globals — no allocation allowed)
__device__ float g_deg[N_NODES];
__device__ float g_dinv[N_NODES];
__device__ float g_A[(size_t)N_NODES * HID];   // GEMM output (messages h)
__device__ float g_B[(size_t)N_NODES * HID];   // aggregation buffer
__device__ float g_pool[N_GRAPHS * HID];
__device__ float g_cnt[N_GRAPHS];

__device__ __forceinline__ void red_add_v4(float* addr, float4 v) {
    asm volatile("red.global.add.v4.f32 [%0], {%1,%2,%3,%4};"
                 :: "l"(addr), "f"(v.x), "f"(v.y), "f"(v.z), "f"(v.w)
                 : "memory");
}

// ---------------- zero deg / pool / cnt ----------------
__global__ void zero_kernel() {
    int i = blockIdx.x * blockDim.x + threadIdx.x;
    if (i < N_NODES) g_deg[i] = 0.0f;
    if (i < N_GRAPHS * HID) g_pool[i] = 0.0f;
    if (i < N_GRAPHS) g_cnt[i] = 0.0f;
}

// ---------------- degree at dst ----------------
__global__ void deg_kernel(const int* __restrict__ dst) {
    int e = blockIdx.x * blockDim.x + threadIdx.x;
    if (e < N_EDGES) atomicAdd(&g_deg[dst[e]], 1.0f);
}

__global__ void dinv_kernel() {
    int i = blockIdx.x * blockDim.x + threadIdx.x;
    if (i < N_NODES) g_dinv[i] = rsqrtf(g_deg[i] + 1.0f);
}

// ---------------- GEMM1: g_A = x @ W1  (N x 12 @ 12 x 64) ----------------
// 4 threads per row, 16 outputs each.
__global__ void gemm1_kernel(const float* __restrict__ x, const float* __restrict__ W1) {
    __shared__ float Ws[IN_CH * HID];  // 768
    for (int i = threadIdx.x; i < IN_CH * HID; i += blockDim.x) Ws[i] = W1[i];
    __syncthreads();
    int gt = blockIdx.x * blockDim.x + threadIdx.x;
    int row = gt >> 2;
    int cb  = (gt & 3) << 4;
    const float* xr = x + (size_t)row * IN_CH;
    float acc[16];
#pragma unroll
    for (int j = 0; j < 16; j++) acc[j] = 0.0f;
#pragma unroll
    for (int k = 0; k < IN_CH; k++) {
        float xv = __ldg(xr + k);
#pragma unroll
        for (int j = 0; j < 16; j++) acc[j] = fmaf(xv, Ws[k * HID + cb + j], acc[j]);
    }
    float* o = g_A + (size_t)row * HID + cb;
#pragma unroll
    for (int j = 0; j < 16; j += 4)
        *(float4*)(o + j) = make_float4(acc[j], acc[j + 1], acc[j + 2], acc[j + 3]);
}

// ---------------- init B with self-loop + bias:  B = A*dinv^2 + b ----------------
__global__ void init_self_kernel(const float* __restrict__ bias) {
    int t = blockIdx.x * blockDim.x + threadIdx.x;
    int node = t >> 4;
    int c = (t & 15) << 2;
    float di = g_dinv[node];
    float s = di * di;
    float4 v = *(const float4*)(g_A + (size_t)node * HID + c);
    float4 b = *(const float4*)(bias + c);
    float4 r;
    r.x = fmaf(v.x, s, b.x);
    r.y = fmaf(v.y, s, b.y);
    r.z = fmaf(v.z, s, b.z);
    r.w = fmaf(v.w, s, b.w);
    *(float4*)(g_B + (size_t)node * HID + c) = r;
}

// ---------------- edge scatter: B[dst] += A[src] * dinv[src]*dinv[dst] ----------------
// 16 threads per edge, float4 each, vector red.
__global__ void scatter_kernel(const int* __restrict__ src, const int* __restrict__ dst) {
    int t = blockIdx.x * blockDim.x + threadIdx.x;
    int e = t >> 4;
    int c = (t & 15) << 2;
    int s = __ldg(src + e);   // lanes 0-15 broadcast (same address)
    int d = __ldg(dst + e);
    float nrm = __ldg(g_dinv + s) * __ldg(g_dinv + d);
    float4 v = *(const float4*)(g_A + (size_t)s * HID + c);
    v.x *= nrm; v.y *= nrm; v.z *= nrm; v.w *= nrm;
    red_add_v4(g_B + (size_t)d * HID + c, v);
}

// ---------------- GEMM2: g_A = relu(g_B) @ W2  (N x 64 @ 64 x 64) ----------------
// 64 rows per block of 256 threads; 4 threads per row, 16 outputs each.
__global__ void gemm2_kernel(const float* __restrict__ W2) {
    __shared__ float Ws[HID * HID];          // 16 KB
    __shared__ float rows[64 * 68];          // padded pitch 68, 17 KB
    int tid = threadIdx.x;
    for (int i = tid; i < HID * HID; i += 256) Ws[i] = W2[i];
    int rbase = blockIdx.x * 64;
    // stage 64 input rows with ReLU
    for (int i = tid * 4; i < 64 * 64; i += 256 * 4) {
        int r = i >> 6, cc = i & 63;
        float4 v = *(const float4*)(g_B + (size_t)(rbase + r) * HID + cc);
        v.x = fmaxf(v.x, 0.0f); v.y = fmaxf(v.y, 0.0f);
        v.z = fmaxf(v.z, 0.0f); v.w = fmaxf(v.w, 0.0f);
        *(float4*)(rows + r * 68 + cc) = v;
    }
    __syncthreads();
    int r = tid >> 2;
    int cb = (tid & 3) << 4;
    float4 a0 = make_float4(0, 0, 0, 0), a1 = a0, a2 = a0, a3 = a0;
#pragma unroll
    for (int k = 0; k < HID; k++) {
        float xv = rows[r * 68 + k];
        const float4* w = (const float4*)&Ws[k * HID + cb];
        float4 w0 = w[0], w1 = w[1], w2 = w[2], w3 = w[3];
        a0.x = fmaf(xv, w0.x, a0.x); a0.y = fmaf(xv, w0.y, a0.y);
        a0.z = fmaf(xv, w0.z, a0.z); a0.w = fmaf(xv, w0.w, a0.w);
        a1.x = fmaf(xv, w1.x, a1.x); a1.y = fmaf(xv, w1.y, a1.y);
        a1.z = fmaf(xv, w1.z, a1.z); a1.w = fmaf(xv, w1.w, a1.w);
        a2.x = fmaf(xv, w2.x, a2.x); a2.y = fmaf(xv, w2.y, a2.y);
        a2.z = fmaf(xv, w2.z, a2.z); a2.w = fmaf(xv, w2.w, a2.w);
        a3.x = fmaf(xv, w3.x, a3.x); a3.y = fmaf(xv, w3.y, a3.y);
        a3.z = fmaf(xv, w3.z, a3.z); a3.w = fmaf(xv, w3.w, a3.w);
    }
    float* o = g_A + (size_t)(rbase + r) * HID + cb;
    ((float4*)o)[0] = a0; ((float4*)o)[1] = a1;
    ((float4*)o)[2] = a2; ((float4*)o)[3] = a3;
}

// ---------------- graph counts ----------------
__global__ void cnt_kernel(const int* __restrict__ batch) {
    int i = blockIdx.x * blockDim.x + threadIdx.x;
    if (i < N_NODES) atomicAdd(&g_cnt[batch[i]], 1.0f);
}

// ---------------- pool: g_pool[batch[i]] += relu(B[i]) ----------------
__global__ void pool_kernel(const int* __restrict__ batch) {
    int t = blockIdx.x * blockDim.x + threadIdx.x;
    int node = t >> 4;
    int c = (t & 15) << 2;
    int g = __ldg(batch + node);
    float4 v = *(const float4*)(g_B + (size_t)node * HID + c);
    v.x = fmaxf(v.x, 0.0f); v.y = fmaxf(v.y, 0.0f);
    v.z = fmaxf(v.z, 0.0f); v.w = fmaxf(v.w, 0.0f);
    red_add_v4(g_pool + g * HID + c, v);
}

// ---------------- head: out = sigmoid((pool/cnt) @ Wfc + bfc) ----------------
__global__ void head_kernel(const float* __restrict__ Wfc, const float* __restrict__ bfc,
                            float* __restrict__ out) {
    __shared__ float Wf[HID * OUT_CH];  // 256
    if (threadIdx.x < HID * OUT_CH) Wf[threadIdx.x] = Wfc[threadIdx.x];
    __syncthreads();
    int gt = blockIdx.x * blockDim.x + threadIdx.x;
    int g = gt >> 2;
    int o = gt & 3;
    float cnt = fmaxf(g_cnt[g], 1.0f);
    float inv = 1.0f / cnt;
    float s = 0.0f;
#pragma unroll
    for (int k = 0; k < HID; k++) s = fmaf(g_pool[g * HID + k], Wf[k * OUT_CH + o], s);
    s = fmaf(s, inv, bfc[o]);
    out[gt] = 1.0f / (1.0f + expf(-s));
}

extern "C" void kernel_launch(void* const* d_in, const int* in_sizes, int n_in,
                              void* d_out, int out_size) {
    const float* x   = (const float*)d_in[0];
    const int*   ei  = (const int*)d_in[1];   // [2, E] int32 (JAX x64 disabled)
    const int*   bat = (const int*)d_in[2];
    const float* W1  = (const float*)d_in[3];
    const float* b1  = (const float*)d_in[4];
    const float* W2  = (const float*)d_in[5];
    const float* b2  = (const float*)d_in[6];
    const float* Wfc = (const float*)d_in[7];
    const float* bfc = (const float*)d_in[8];
    float* out = (float*)d_out;

    const int* src = ei;
    const int* dst = ei + N_EDGES;

    const int B = 256;

    // zero deg / pool / cnt
    zero_kernel<<<(N_GRAPHS * HID + B - 1) / B, B>>>();
    // degree + dinv
    deg_kernel<<<N_EDGES / B, B>>>(dst);
    dinv_kernel<<<N_NODES / B, B>>>();

    // layer 1
    gemm1_kernel<<<(N_NODES * 4) / B, B>>>(x, W1);
    init_self_kernel<<<(N_NODES * 16) / B, B>>>(b1);
    scatter_kernel<<<(N_EDGES * 16) / B, B>>>(src, dst);

    // layer 2 (relu of B applied inside gemm2)
    gemm2_kernel<<<N_NODES / 64, B>>>(W2);
    init_self_kernel<<<(N_NODES * 16) / B, B>>>(b2);
    scatter_kernel<<<(N_EDGES * 16) / B, B>>>(src, dst);

    // pooling (relu applied inside pool)
    cnt_kernel<<<N_NODES / B, B>>>(bat);
    pool_kernel<<<(N_NODES * 16) / B, B>>>(bat);

    // head
    head_kernel<<<(N_GRAPHS * OUT_CH) / B, B>>>(Wfc, bfc, out);
}

// round 3
// speedup vs baseline: 1.2932x; 1.2932x over previous
#include <cuda_runtime.h>
#include <cuda_bf16.h>
#include <math.h>

#define N_NODES 131072
#define N_EDGES 2097152
#define N_GRAPHS 2048
#define IN_CH 12
#define HID 64
#define OUT_CH 4

// Scratch (device globals — no allocation allowed).
// NOTE: these are referenced ONLY inside device code (passing a __device__
// symbol as a host-side kernel argument takes the host shadow address — on
// GB300 ATS that silently reads host memory; that was the R2 bug).
__device__ int   g_degi[N_NODES];
__device__ float g_dinv[N_NODES];
__device__ int   g_rowstart[N_NODES];
__device__ int   g_cursor[N_NODES];
__device__ int   g_total;
__device__ int2  g_csr[N_EDGES];               // .x = src, .y = float bits of norm
__device__ float g_A[(size_t)N_NODES * HID];   // GEMM output (messages h)
__device__ float g_B[(size_t)N_NODES * HID];   // layer-1 aggregation output
__device__ float g_pool[N_GRAPHS * HID];
__device__ float g_cnt[N_GRAPHS];

__device__ __forceinline__ void red_add_v4(float* addr, float4 v) {
    asm volatile("red.global.add.v4.f32 [%0], {%1,%2,%3,%4};"
                 :: "l"(addr), "f"(v.x), "f"(v.y), "f"(v.z), "f"(v.w)
                 : "memory");
}

// ---------------- zero deg / pool / cnt / total ----------------
__global__ void zero_kernel() {
    int i = blockIdx.x * blockDim.x + threadIdx.x;
    if (i < N_NODES) g_degi[i] = 0;
    if (i < N_GRAPHS * HID) g_pool[i] = 0.0f;
    if (i < N_GRAPHS) g_cnt[i] = 0.0f;
    if (i == 0) g_total = 0;
}

// ---------------- degree at dst (int) ----------------
__global__ void deg_kernel(const int* __restrict__ dst) {
    int e = blockIdx.x * blockDim.x + threadIdx.x;
    if (e < N_EDGES) atomicAdd(&g_degi[dst[e]], 1);
}

// ---------------- dinv + warp-aggregated unordered scan -> rowstart/cursor ----------------
__global__ void scan_kernel() {
    int i = blockIdx.x * blockDim.x + threadIdx.x;
    int lane = threadIdx.x & 31;
    int d = g_degi[i];
    g_dinv[i] = rsqrtf((float)d + 1.0f);
    int v = d;
#pragma unroll
    for (int o = 1; o < 32; o <<= 1) {
        int t = __shfl_up_sync(0xFFFFFFFFu, v, o);
        if (lane >= o) v += t;
    }
    int total = __shfl_sync(0xFFFFFFFFu, v, 31);
    int base = 0;
    if (lane == 0) base = atomicAdd(&g_total, total);
    base = __shfl_sync(0xFFFFFFFFu, base, 0);
    int start = base + v - d;
    g_rowstart[i] = start;
    g_cursor[i] = start;
}

// ---------------- fill CSR: (src, norm) per edge, grouped by dst ----------------
__global__ void fill_kernel(const int* __restrict__ src, const int* __restrict__ dst) {
    int e = blockIdx.x * blockDim.x + threadIdx.x;
    int s = src[e];
    int d = dst[e];
    float nrm = __ldg(g_dinv + s) * __ldg(g_dinv + d);
    int pos = atomicAdd(&g_cursor[d], 1);
    g_csr[pos] = make_int2(s, __float_as_int(nrm));
}

// ---------------- GEMM1: g_A = x @ W1  (N x 12 @ 12 x 64) ----------------
__global__ void gemm1_kernel(const float* __restrict__ x, const float* __restrict__ W1) {
    __shared__ float Ws[IN_CH * HID];   // 768
    __shared__ float Xs[64 * IN_CH];    // 768
    int tid = threadIdx.x;
    for (int i = tid; i < IN_CH * HID; i += 256) Ws[i] = W1[i];
    const float* xb = x + (size_t)blockIdx.x * 64 * IN_CH;
    for (int i = tid; i < 64 * IN_CH; i += 256) Xs[i] = xb[i];
    __syncthreads();
    int row = tid >> 2;
    int cb  = (tid & 3) << 4;
    float acc[16];
#pragma unroll
    for (int j = 0; j < 16; j++) acc[j] = 0.0f;
#pragma unroll
    for (int k = 0; k < IN_CH; k++) {
        float xv = Xs[row * IN_CH + k];
#pragma unroll
        for (int j = 0; j < 16; j++) acc[j] = fmaf(xv, Ws[k * HID + cb + j], acc[j]);
    }
    float* o = g_A + (size_t)(blockIdx.x * 64 + row) * HID + cb;
#pragma unroll
    for (int j = 0; j < 16; j += 4)
        *(float4*)(o + j) = make_float4(acc[j], acc[j + 1], acc[j + 2], acc[j + 3]);
}

// ---------------- aggregation: warp per node, CSR gather (reads g_A internally) ----
// MODE 0: g_B[node] = sum + self + bias                        (layer 1)
// MODE 1: red(g_pool[batch[node]] += relu(sum + self + bias))  (layer 2, fused pool)
template <int MODE>
__global__ void agg_kernel(const float* __restrict__ bias, const int* __restrict__ batch) {
    const float* h = g_A;   // device-side symbol reference (correct address space)
    int node = blockIdx.x * 8 + (threadIdx.x >> 5);
    int lane = threadIdx.x & 31;
    int c  = (lane & 15) << 2;   // float column base
    int half = lane >> 4;        // which edge of the pair
    int beg = g_rowstart[node];
    int end = beg + g_degi[node];
    float4 acc = make_float4(0.f, 0.f, 0.f, 0.f);
    if (half == 0) {
        float di = g_dinv[node];
        float s = di * di;
        float4 v = *(const float4*)(h + (size_t)node * HID + c);
        acc.x = v.x * s; acc.y = v.y * s; acc.z = v.z * s; acc.w = v.w * s;
    }
    for (int e = beg + half; e < end; e += 2) {
        int2 pr = __ldg(g_csr + e);
        float nrm = __int_as_float(pr.y);
        float4 v = *(const float4*)(h + (size_t)pr.x * HID + c);
        acc.x = fmaf(v.x, nrm, acc.x);
        acc.y = fmaf(v.y, nrm, acc.y);
        acc.z = fmaf(v.z, nrm, acc.z);
        acc.w = fmaf(v.w, nrm, acc.w);
    }
    acc.x += __shfl_down_sync(0xFFFFFFFFu, acc.x, 16);
    acc.y += __shfl_down_sync(0xFFFFFFFFu, acc.y, 16);
    acc.z += __shfl_down_sync(0xFFFFFFFFu, acc.z, 16);
    acc.w += __shfl_down_sync(0xFFFFFFFFu, acc.w, 16);
    if (half == 0) {
        float4 b = *(const float4*)(bias + c);
        acc.x += b.x; acc.y += b.y; acc.z += b.z; acc.w += b.w;
        if (MODE == 0) {
            *(float4*)(g_B + (size_t)node * HID + c) = acc;
        } else {
            acc.x = fmaxf(acc.x, 0.f); acc.y = fmaxf(acc.y, 0.f);
            acc.z = fmaxf(acc.z, 0.f); acc.w = fmaxf(acc.w, 0.f);
            int g = __ldg(batch + node);
            red_add_v4(g_pool + g * HID + c, acc);
        }
    }
}

// ---------------- GEMM2: g_A = relu(g_B) @ W2  (N x 64 @ 64 x 64) ----------------
__global__ void gemm2_kernel(const float* __restrict__ W2) {
    __shared__ float Ws[HID * HID];
    __shared__ float rows[64 * 68];
    int tid = threadIdx.x;
    for (int i = tid; i < HID * HID; i += 256) Ws[i] = W2[i];
    int rbase = blockIdx.x * 64;
    for (int i = tid * 4; i < 64 * 64; i += 256 * 4) {
        int r = i >> 6, cc = i & 63;
        float4 v = *(const float4*)(g_B + (size_t)(rbase + r) * HID + cc);
        v.x = fmaxf(v.x, 0.0f); v.y = fmaxf(v.y, 0.0f);
        v.z = fmaxf(v.z, 0.0f); v.w = fmaxf(v.w, 0.0f);
        *(float4*)(rows + r * 68 + cc) = v;
    }
    __syncthreads();
    int r = tid >> 2;
    int cb = (tid & 3) << 4;
    float4 a0 = make_float4(0, 0, 0, 0), a1 = a0, a2 = a0, a3 = a0;
#pragma unroll
    for (int k = 0; k < HID; k++) {
        float xv = rows[r * 68 + k];
        const float4* w = (const float4*)&Ws[k * HID + cb];
        float4 w0 = w[0], w1 = w[1], w2 = w[2], w3 = w[3];
        a0.x = fmaf(xv, w0.x, a0.x); a0.y = fmaf(xv, w0.y, a0.y);
        a0.z = fmaf(xv, w0.z, a0.z); a0.w = fmaf(xv, w0.w, a0.w);
        a1.x = fmaf(xv, w1.x, a1.x); a1.y = fmaf(xv, w1.y, a1.y);
        a1.z = fmaf(xv, w1.z, a1.z); a1.w = fmaf(xv, w1.w, a1.w);
        a2.x = fmaf(xv, w2.x, a2.x); a2.y = fmaf(xv, w2.y, a2.y);
        a2.z = fmaf(xv, w2.z, a2.z); a2.w = fmaf(xv, w2.w, a2.w);
        a3.x = fmaf(xv, w3.x, a3.x); a3.y = fmaf(xv, w3.y, a3.y);
        a3.z = fmaf(xv, w3.z, a3.z); a3.w = fmaf(xv, w3.w, a3.w);
    }
    float* o = g_A + (size_t)(rbase + r) * HID + cb;
    ((float4*)o)[0] = a0; ((float4*)o)[1] = a1;
    ((float4*)o)[2] = a2; ((float4*)o)[3] = a3;
}

// ---------------- graph counts (warp-aggregated; batch is sorted) ----------------
__global__ void cnt_kernel(const int* __restrict__ batch) {
    int i = blockIdx.x * blockDim.x + threadIdx.x;
    int g = batch[i];
    unsigned mask = __match_any_sync(0xFFFFFFFFu, g);
    int leader = __ffs(mask) - 1;
    if ((threadIdx.x & 31) == leader)
        atomicAdd(&g_cnt[g], (float)__popc(mask));
}

// ---------------- head: out = sigmoid((pool/cnt) @ Wfc + bfc) ----------------
__global__ void head_kernel(const float* __restrict__ Wfc, const float* __restrict__ bfc,
                            float* __restrict__ out) {
    __shared__ float Wf[HID * OUT_CH];
    if (threadIdx.x < HID * OUT_CH) Wf[threadIdx.x] = Wfc[threadIdx.x];
    __syncthreads();
    int gt = blockIdx.x * blockDim.x + threadIdx.x;
    int g = gt >> 2;
    int o = gt & 3;
    float cnt = fmaxf(g_cnt[g], 1.0f);
    float inv = 1.0f / cnt;
    float s = 0.0f;
#pragma unroll
    for (int k = 0; k < HID; k++) s = fmaf(g_pool[g * HID + k], Wf[k * OUT_CH + o], s);
    s = fmaf(s, inv, bfc[o]);
    out[gt] = 1.0f / (1.0f + expf(-s));
}

extern "C" void kernel_launch(void* const* d_in, const int* in_sizes, int n_in,
                              void* d_out, int out_size) {
    const float* x   = (const float*)d_in[0];
    const int*   ei  = (const int*)d_in[1];
    const int*   bat = (const int*)d_in[2];
    const float* W1  = (const float*)d_in[3];
    const float* b1  = (const float*)d_in[4];
    const float* W2  = (const float*)d_in[5];
    const float* b2  = (const float*)d_in[6];
    const float* Wfc = (const float*)d_in[7];
    const float* bfc = (const float*)d_in[8];
    float* out = (float*)d_out;

    const int* src = ei;
    const int* dst = ei + N_EDGES;
    const int B = 256;

    zero_kernel<<<(N_NODES + B - 1) / B, B>>>();
    deg_kernel<<<N_EDGES / B, B>>>(dst);
    scan_kernel<<<N_NODES / B, B>>>();
    fill_kernel<<<N_EDGES / B, B>>>(src, dst);

    // layer 1: gemm1 -> CSR gather-aggregate (self+bias fused)
    gemm1_kernel<<<N_NODES / 64, B>>>(x, W1);
    agg_kernel<0><<<N_NODES / 8, B>>>(b1, bat);

    // layer 2: gemm2 (ReLU fused on load) -> gather-aggregate fused with pooling
    gemm2_kernel<<<N_NODES / 64, B>>>(W2);
    agg_kernel<1><<<N_NODES / 8, B>>>(b2, bat);

    cnt_kernel<<<N_NODES / B, B>>>(bat);
    head_kernel<<<(N_GRAPHS * OUT_CH) / B, B>>>(Wfc, bfc, out);
}

// round 6
// speedup vs baseline: 1.5507x; 1.1991x over previous
#include <cuda_runtime.h>
#include <cuda_fp16.h>
#include <cstdint>
#include <math.h>

#define N_NODES 131072
#define N_EDGES 2097152
#define N_GRAPHS 2048
#define IN_CH 12
#define HID 64
#define OUT_CH 4

// Scratch (device globals — no allocation allowed).
// Referenced ONLY inside device code (host-side use of __device__ symbols
// takes the host shadow address under ATS — the R2 bug).
__device__ int   g_degi[N_NODES];
__device__ float g_dinv[N_NODES];
__device__ int   g_rowstart[N_NODES];
__device__ int   g_cursor[N_NODES];
__device__ int   g_total;
__device__ int2  g_csr[N_EDGES];                       // .x = src, .y = float bits of norm
__device__ uint4 g_Ah_raw[(size_t)N_NODES * HID / 8];  // h as __half [N, 64], 16B-aligned
__device__ float g_B[(size_t)N_NODES * HID];           // layer-1 aggregation output (fp32)
__device__ float g_pool[N_GRAPHS * HID];
__device__ float g_cnt[N_GRAPHS];

__device__ __forceinline__ void red_add_v4(float* addr, float4 v) {
    asm volatile("red.global.add.v4.f32 [%0], {%1,%2,%3,%4};"
                 :: "l"(addr), "f"(v.x), "f"(v.y), "f"(v.z), "f"(v.w)
                 : "memory");
}

__device__ __forceinline__ unsigned int pack_half2(float a, float b) {
    __half2 h = __floats2half2_rn(a, b);
    return *(unsigned int*)&h;
}

// ---------------- zero deg / pool / cnt / total ----------------
__global__ void zero_kernel() {
    int i = blockIdx.x * blockDim.x + threadIdx.x;
    if (i < N_NODES) g_degi[i] = 0;
    if (i < N_GRAPHS * HID) g_pool[i] = 0.0f;
    if (i < N_GRAPHS) g_cnt[i] = 0.0f;
    if (i == 0) g_total = 0;
}

// ---------------- degree at dst (int) ----------------
__global__ void deg_kernel(const int* __restrict__ dst) {
    int e = blockIdx.x * blockDim.x + threadIdx.x;
    if (e < N_EDGES) atomicAdd(&g_degi[dst[e]], 1);
}

// ---------------- dinv + warp-aggregated unordered scan -> rowstart/cursor ----------------
__global__ void scan_kernel() {
    int i = blockIdx.x * blockDim.x + threadIdx.x;
    int lane = threadIdx.x & 31;
    int d = g_degi[i];
    g_dinv[i] = rsqrtf((float)d + 1.0f);
    int v = d;
#pragma unroll
    for (int o = 1; o < 32; o <<= 1) {
        int t = __shfl_up_sync(0xFFFFFFFFu, v, o);
        if (lane >= o) v += t;
    }
    int total = __shfl_sync(0xFFFFFFFFu, v, 31);
    int base = 0;
    if (lane == 0) base = atomicAdd(&g_total, total);
    base = __shfl_sync(0xFFFFFFFFu, base, 0);
    int start = base + v - d;
    g_rowstart[i] = start;
    g_cursor[i] = start;
}

// ---------------- fill CSR: (src, norm) per edge, grouped by dst ----------------
__global__ void fill_kernel(const int* __restrict__ src, const int* __restrict__ dst) {
    int e = blockIdx.x * blockDim.x + threadIdx.x;
    int s = src[e];
    int d = dst[e];
    float nrm = __ldg(g_dinv + s) * __ldg(g_dinv + d);
    int pos = atomicAdd(&g_cursor[d], 1);
    g_csr[pos] = make_int2(s, __float_as_int(nrm));
}

// ---------------- GEMM1: g_Ah = half(x @ W1)  (N x 12 @ 12 x 64) ----------------
__global__ void gemm1_kernel(const float* __restrict__ x, const float* __restrict__ W1) {
    __shared__ float Ws[IN_CH * HID];   // 768
    __shared__ float Xs[64 * IN_CH];    // 768
    int tid = threadIdx.x;
    for (int i = tid; i < IN_CH * HID; i += 256) Ws[i] = W1[i];
    const float* xb = x + (size_t)blockIdx.x * 64 * IN_CH;
    for (int i = tid; i < 64 * IN_CH; i += 256) Xs[i] = xb[i];
    __syncthreads();
    int row = tid >> 2;
    int cb  = (tid & 3) << 4;
    float acc[16];
#pragma unroll
    for (int j = 0; j < 16; j++) acc[j] = 0.0f;
#pragma unroll
    for (int k = 0; k < IN_CH; k++) {
        float xv = Xs[row * IN_CH + k];
#pragma unroll
        for (int j = 0; j < 16; j++) acc[j] = fmaf(xv, Ws[k * HID + cb + j], acc[j]);
    }
    // pack 16 floats -> 8 half2 -> two uint4 stores
    __half* Ah = (__half*)g_Ah_raw;
    unsigned int p[8];
#pragma unroll
    for (int j = 0; j < 8; j++) p[j] = pack_half2(acc[2 * j], acc[2 * j + 1]);
    uint4* o = (uint4*)(Ah + (size_t)(blockIdx.x * 64 + row) * HID + cb);
    o[0] = make_uint4(p[0], p[1], p[2], p[3]);
    o[1] = make_uint4(p[4], p[5], p[6], p[7]);
}

// ---------------- aggregation: warp per node, CSR gather of half features --------
// MODE 0: g_B[node] = sum + self + bias                        (layer 1)
// MODE 1: red(g_pool[batch[node]] += relu(sum + self + bias))  (layer 2, fused pool)
template <int MODE>
__global__ void agg_kernel(const float* __restrict__ bias, const int* __restrict__ batch) {
    const __half* h = (const __half*)g_Ah_raw;
    int node = blockIdx.x * 8 + (threadIdx.x >> 5);
    int lane = threadIdx.x & 31;
    int c  = (lane & 15) << 2;   // column base (4 halves per lane)
    int hid = lane >> 4;         // which edge of the pair
    int beg = g_rowstart[node];
    int end = beg + g_degi[node];
    float4 acc = make_float4(0.f, 0.f, 0.f, 0.f);
    if (hid == 0) {
        float di = g_dinv[node];
        float s = di * di;
        uint2 u = *(const uint2*)(h + (size_t)node * HID + c);
        float2 lo = __half22float2(*(__half2*)&u.x);
        float2 hi2 = __half22float2(*(__half2*)&u.y);
        acc.x = lo.x * s; acc.y = lo.y * s; acc.z = hi2.x * s; acc.w = hi2.y * s;
    }
    for (int e = beg + hid; e < end; e += 2) {
        int2 pr = __ldg(g_csr + e);
        float nrm = __int_as_float(pr.y);
        uint2 u = __ldg((const uint2*)(h + (size_t)pr.x * HID + c));
        float2 lo = __half22float2(*(__half2*)&u.x);
        float2 hi2 = __half22float2(*(__half2*)&u.y);
        acc.x = fmaf(lo.x,  nrm, acc.x);
        acc.y = fmaf(lo.y,  nrm, acc.y);
        acc.z = fmaf(hi2.x, nrm, acc.z);
        acc.w = fmaf(hi2.y, nrm, acc.w);
    }
    acc.x += __shfl_down_sync(0xFFFFFFFFu, acc.x, 16);
    acc.y += __shfl_down_sync(0xFFFFFFFFu, acc.y, 16);
    acc.z += __shfl_down_sync(0xFFFFFFFFu, acc.z, 16);
    acc.w += __shfl_down_sync(0xFFFFFFFFu, acc.w, 16);
    if (hid == 0) {
        float4 b = *(const float4*)(bias + c);
        acc.x += b.x; acc.y += b.y; acc.z += b.z; acc.w += b.w;
        if (MODE == 0) {
            *(float4*)(g_B + (size_t)node * HID + c) = acc;
        } else {
            acc.x = fmaxf(acc.x, 0.f); acc.y = fmaxf(acc.y, 0.f);
            acc.z = fmaxf(acc.z, 0.f); acc.w = fmaxf(acc.w, 0.f);
            int g = __ldg(batch + node);
            red_add_v4(g_pool + g * HID + c, acc);
        }
    }
}

// ---------------- GEMM2: g_Ah = half(relu(g_B) @ W2)  (N x 64 @ 64 x 64) --------
__global__ void gemm2_kernel(const float* __restrict__ W2) {
    __shared__ float Ws[HID * HID];
    __shared__ float rows[64 * 68];
    int tid = threadIdx.x;
    for (int i = tid; i < HID * HID; i += 256) Ws[i] = W2[i];
    int rbase = blockIdx.x * 64;
    for (int i = tid * 4; i < 64 * 64; i += 256 * 4) {
        int r = i >> 6, cc = i & 63;
        float4 v = *(const float4*)(g_B + (size_t)(rbase + r) * HID + cc);
        v.x = fmaxf(v.x, 0.0f); v.y = fmaxf(v.y, 0.0f);
        v.z = fmaxf(v.z, 0.0f); v.w = fmaxf(v.w, 0.0f);
        *(float4*)(rows + r * 68 + cc) = v;
    }
    __syncthreads();
    int r = tid >> 2;
    int cb = (tid & 3) << 4;
    float acc[16];
#pragma unroll
    for (int j = 0; j < 16; j++) acc[j] = 0.0f;
#pragma unroll
    for (int k = 0; k < HID; k++) {
        float xv = rows[r * 68 + k];
        const float4* w = (const float4*)&Ws[k * HID + cb];
#pragma unroll
        for (int q = 0; q < 4; q++) {
            float4 wv = w[q];
            acc[4 * q + 0] = fmaf(xv, wv.x, acc[4 * q + 0]);
            acc[4 * q + 1] = fmaf(xv, wv.y, acc[4 * q + 1]);
            acc[4 * q + 2] = fmaf(xv, wv.z, acc[4 * q + 2]);
            acc[4 * q + 3] = fmaf(xv, wv.w, acc[4 * q + 3]);
        }
    }
    __half* Ah = (__half*)g_Ah_raw;
    unsigned int p[8];
#pragma unroll
    for (int j = 0; j < 8; j++) p[j] = pack_half2(acc[2 * j], acc[2 * j + 1]);
    uint4* o = (uint4*)(Ah + (size_t)(rbase + r) * HID + cb);
    o[0] = make_uint4(p[0], p[1], p[2], p[3]);
    o[1] = make_uint4(p[4], p[5], p[6], p[7]);
}

// ---------------- graph counts (warp-aggregated; batch is sorted) ----------------
__global__ void cnt_kernel(const int* __restrict__ batch) {
    int i = blockIdx.x * blockDim.x + threadIdx.x;
    int g = batch[i];
    unsigned mask = __match_any_sync(0xFFFFFFFFu, g);
    int leader = __ffs(mask) - 1;
    if ((threadIdx.x & 31) == leader)
        atomicAdd(&g_cnt[g], (float)__popc(mask));
}

// ---------------- head: out = sigmoid((pool/cnt) @ Wfc + bfc) ----------------
__global__ void head_kernel(const float* __restrict__ Wfc, const float* __restrict__ bfc,
                            float* __restrict__ out) {
    __shared__ float Wf[HID * OUT_CH];
    if (threadIdx.x < HID * OUT_CH) Wf[threadIdx.x] = Wfc[threadIdx.x];
    __syncthreads();
    int gt = blockIdx.x * blockDim.x + threadIdx.x;
    int g = gt >> 2;
    int o = gt & 3;
    float cnt = fmaxf(g_cnt[g], 1.0f);
    float inv = 1.0f / cnt;
    float s = 0.0f;
#pragma unroll
    for (int k = 0; k < HID; k++) s = fmaf(g_pool[g * HID + k], Wf[k * OUT_CH + o], s);
    s = fmaf(s, inv, bfc[o]);
    out[gt] = 1.0f / (1.0f + expf(-s));
}

extern "C" void kernel_launch(void* const* d_in, const int* in_sizes, int n_in,
                              void* d_out, int out_size) {
    const float* x   = (const float*)d_in[0];
    const int*   ei  = (const int*)d_in[1];
    const int*   bat = (const int*)d_in[2];
    const float* W1  = (const float*)d_in[3];
    const float* b1  = (const float*)d_in[4];
    const float* W2  = (const float*)d_in[5];
    const float* b2  = (const float*)d_in[6];
    const float* Wfc = (const float*)d_in[7];
    const float* bfc = (const float*)d_in[8];
    float* out = (float*)d_out;

    const int* src = ei;
    const int* dst = ei + N_EDGES;
    const int B = 256;

    zero_kernel<<<(N_NODES + B - 1) / B, B>>>();
    deg_kernel<<<N_EDGES / B, B>>>(dst);
    scan_kernel<<<N_NODES / B, B>>>();
    fill_kernel<<<N_EDGES / B, B>>>(src, dst);

    // layer 1: gemm1 (half output) -> CSR gather-aggregate (self+bias fused)
    gemm1_kernel<<<N_NODES / 64, B>>>(x, W1);
    agg_kernel<0><<<N_NODES / 8, B>>>(b1, bat);

    // layer 2: gemm2 (ReLU on load, half output) -> gather-aggregate fused with pooling
    gemm2_kernel<<<N_NODES / 64, B>>>(W2);
    agg_kernel<1><<<N_NODES / 8, B>>>(b2, bat);

    cnt_kernel<<<N_NODES / B, B>>>(bat);
    head_kernel<<<(N_GRAPHS * OUT_CH) / B, B>>>(Wfc, bfc, out);
}